// round 9
// baseline (speedup 1.0000x reference)
#include <cuda_runtime.h>
#include <cuda_bf16.h>
#include <math.h>

#define BT    256
#define NCOLS 5000
#define NVEC  1250      // NCOLS/4
#define NVPAD 1280      // ceil to multiple of BT (uniform warp trips for ballot)
#define TOPK  10
#define MAXB  8192
#define CAP   512

__device__ float        g_row[MAXB];
__device__ unsigned int g_ctr = 0;

// Order-preserving float->uint bijection: f1<f2  <=>  ordf(f1)<ordf(f2)
__device__ __forceinline__ unsigned int ordf(float f) {
    unsigned int u = __float_as_uint(f);
    return (u & 0x80000000u) ? ~u : (u | 0x80000000u);
}

__device__ __forceinline__ int blockSumI(int v, int* sc) {
    int lane = threadIdx.x & 31, w = threadIdx.x >> 5;
#pragma unroll
    for (int o = 16; o; o >>= 1) v += __shfl_down_sync(0xffffffffu, v, o);
    if (lane == 0) sc[w] = v;
    __syncthreads();
    if (w == 0) {
        int x = lane < 8 ? sc[lane] : 0;
#pragma unroll
        for (int o = 4; o; o >>= 1) x += __shfl_down_sync(0xffffffffu, x, o);
        if (lane == 0) sc[0] = x;
    }
    __syncthreads();
    int r = sc[0];
    __syncthreads();
    return r;
}

// Fused block reduce: 8 float sums at once.
__device__ __forceinline__ void blockReduce8F(float v[8], float* scf /*64*/) {
    int lane = threadIdx.x & 31, w = threadIdx.x >> 5;
#pragma unroll
    for (int o = 16; o; o >>= 1) {
#pragma unroll
        for (int j = 0; j < 8; j++)
            v[j] += __shfl_down_sync(0xffffffffu, v[j], o);
    }
    if (lane == 0) {
#pragma unroll
        for (int j = 0; j < 8; j++) scf[j * 8 + w] = v[j];
    }
    __syncthreads();
    if (w == 0) {
        float x[8];
#pragma unroll
        for (int j = 0; j < 8; j++) x[j] = lane < 8 ? scf[j * 8 + lane] : 0.0f;
#pragma unroll
        for (int o = 4; o; o >>= 1) {
#pragma unroll
            for (int j = 0; j < 8; j++)
                x[j] += __shfl_down_sync(0xffffffffu, x[j], o);
        }
        if (lane == 0) {
#pragma unroll
            for (int j = 0; j < 8; j++) scf[j * 8] = x[j];
        }
    }
    __syncthreads();
#pragma unroll
    for (int j = 0; j < 8; j++) v[j] = scf[j * 8];
    __syncthreads();
}

// In-place inclusive prefix scan of a 256-int shared array (BT==256 threads).
__device__ __forceinline__ void scan256(int* h, int* wtot) {
    int tid = threadIdx.x, lane = tid & 31, w = tid >> 5;
    int v = h[tid];
#pragma unroll
    for (int o = 1; o < 32; o <<= 1) {
        int t = __shfl_up_sync(0xffffffffu, v, o);
        if (lane >= o) v += t;
    }
    if (lane == 31) wtot[w] = v;
    __syncthreads();
    if (w == 0 && lane < 8) {
        int x = wtot[lane];
#pragma unroll
        for (int o = 1; o < 8; o <<= 1) {
            int t = __shfl_up_sync(0xffu, x, o);
            if (lane >= o) x += t;
        }
        wtot[lane] = x;
    }
    __syncthreads();
    h[tid] = v + (w ? wtot[w - 1] : 0);
    __syncthreads();
}

// warp max of u64 + broadcast
__device__ __forceinline__ unsigned long long warpMaxBcast(unsigned long long lm) {
#pragma unroll
    for (int o = 16; o; o >>= 1) {
        unsigned long long v = __shfl_down_sync(0xffffffffu, lm, o);
        if (v > lm) lm = v;
    }
    return __shfl_sync(0xffffffffu, lm, 0);
}

__global__ void __launch_bounds__(BT, 6)
row_kernel(const float* __restrict__ up, const float* __restrict__ dn,
           const float* __restrict__ yt, const int* __restrict__ mk,
           float* __restrict__ out)
{
    __shared__ __align__(16) unsigned int s_oy[NVPAD * 4];   // 20.5 KB
    __shared__ int   s_hist[256];
    __shared__ unsigned long long s_ckU[CAP];                // 4 KB
    __shared__ unsigned long long s_ckD[CAP];                // 4 KB
    __shared__ int   s_cnt[2];
    __shared__ int   s_misc[4];   // 0:bU 1:rU 2:bD 3:rD
    __shared__ float s_scf[64];
    __shared__ int   s_sci[8];
    __shared__ int   s_wt[8];
    __shared__ float s_bs[2];
    __shared__ unsigned int s_last;

    const int row = blockIdx.x, tid = threadIdx.x;
    const int lane = tid & 31, w = tid >> 5;
    const size_t base = (size_t)row * NCOLS;
    const float* upr = up + base;
    const float* dnr = dn + base;
    const float* ytr = yt + base;

    s_hist[tid] = 0;
    if (tid < 2) s_cnt[tid] = 0;
    __syncthreads();

    // ---------- P1: the ONE heavy pass. Loads all 4 streams, computes every
    // threshold-independent quantity + stages keys + level-1 histogram. -------
    const float4* y4 = (const float4*)(ytr);
    const float4* u4 = (const float4*)(upr);
    const float4* d4 = (const float4*)(dnr);
    const int4*   m4 = (const int4*)(mk + base);

    int nv = 0;
    float syl = 0.f, sul = 0.f, kac = 0.f, bub = 0.f, bdb = 0.f;

#define P1ELEM(YV, UV, DV, MV, OUT) do {                                     \
        bool v_ = (MV) > 0;                                                  \
        unsigned int o_ = v_ ? ordf(YV) : 0u;                                \
        (OUT) = o_;                                                          \
        unsigned int act_ = __ballot_sync(0xffffffffu, v_);                  \
        if (v_) {                                                            \
            nv++;                                                            \
            float y_ = (YV), u_ = (UV), d_ = (DV);                           \
            float ey_ = __expf(y_);                                          \
            syl += ey_; kac += ey_ * (y_ - u_);                              \
            sul += __expf(u_);                                               \
            bub += fmaxf(u_, 0.f) + __logf(1.f + __expf(-fabsf(u_)));        \
            bdb += fmaxf(d_, 0.f) + __logf(1.f + __expf(-fabsf(d_)));        \
            unsigned int bin_ = o_ >> 24;                                    \
            unsigned int mm_ = __match_any_sync(act_, bin_);                 \
            if ((mm_ & ((1u << lane) - 1u)) == 0u)                           \
                atomicAdd(&s_hist[bin_], (int)__popc(mm_));                  \
        }                                                                    \
    } while (0)

#pragma unroll
    for (int i = tid; i < NVPAD; i += BT) {      // 5 uniform trips
        bool inb = i < NVEC;
        float4 yv = make_float4(0.f, 0.f, 0.f, 0.f);
        float4 uv = yv, dv = yv;
        int4   mv = make_int4(0, 0, 0, 0);
        if (inb) { yv = y4[i]; uv = u4[i]; dv = d4[i]; mv = m4[i]; }
        uint4 ov;
        P1ELEM(yv.x, uv.x, dv.x, mv.x, ov.x);
        P1ELEM(yv.y, uv.y, dv.y, mv.y, ov.y);
        P1ELEM(yv.z, uv.z, dv.z, mv.z, ov.z);
        P1ELEM(yv.w, uv.w, dv.w, mv.w, ov.w);
        ((uint4*)s_oy)[i] = ov;
    }
    __syncthreads();

    nv = blockSumI(nv, s_sci);

    float loss = 0.0f;
    if (nv > 0) {
        const int k = nv < TOPK ? nv : TOPK;

        // ---------- level-1 bin pick, both ends from one histogram -----------
        scan256(s_hist, s_wt);
        {
            int pref = s_hist[tid];
            int cnt  = pref - (tid ? s_hist[tid - 1] : 0);
            if (cnt > 0) {
                int S = nv - pref;                     // strictly above this bin
                if (S < k && S + cnt >= k) { s_misc[0] = tid; s_misc[1] = k - S; }
                int below = pref - cnt;                // strictly below this bin
                if (below < k && pref >= k) { s_misc[2] = tid; s_misc[3] = k - below; }
            }
        }
        __syncthreads();
        const int bU = s_misc[0];
        const int bD = s_misc[2];

        // ---------- P2: trivial smem-only compaction pass --------------------
        // candU: every element whose bin >= bU (contains the whole up top-k).
        // candD: bin <= bD (contains the whole down top-k). ~270 each.
        for (int i = tid; i < NCOLS; i += BT) {
            unsigned int o = s_oy[i];
            if (!o) continue;
            int b1 = (int)(o >> 24);
            if (b1 >= bU) {
                int p = atomicAdd(&s_cnt[0], 1);
                if (p < CAP)
                    s_ckU[p] = ((unsigned long long)o << 32) | (unsigned int)~i;
            }
            if (b1 <= bD) {
                int p = atomicAdd(&s_cnt[1], 1);
                if (p < CAP)
                    s_ckD[p] = ((unsigned long long)(~o) << 32) | (unsigned int)~i;
            }
        }
        __syncthreads();

        // ---------- selection: warp0 = up top-k, warp1 = down top-k ----------
        // k rounds of warp-max give the exact selected set; then <=10 parallel
        // scattered loads fetch the selected logits.
        if (w < 2) {
            const int which = w;
            const int cnt = s_cnt[which];
            const unsigned long long* cand = which ? s_ckD : s_ckU;
            const float* src = which ? dnr : upr;
            unsigned long long mykey = 0ull, thr = ~0ull;
            if (cnt <= CAP) {
                for (int t = 0; t < k; t++) {
                    unsigned long long lm = 0ull;
                    for (int j = lane; j < cnt; j += 32) {
                        unsigned long long kk = cand[j];
                        if (kk < thr && kk > lm) lm = kk;
                    }
                    thr = warpMaxBcast(lm);
                    if (lane == t) mykey = thr;
                }
            } else {   // overflow fallback (not expected): full-array rounds
                const int bb = which ? bD : bU;
                for (int t = 0; t < k; t++) {
                    unsigned long long lm = 0ull;
                    for (int j = lane; j < NCOLS; j += 32) {
                        unsigned int o = s_oy[j];
                        if (!o) continue;
                        int b1 = (int)(o >> 24);
                        if (which ? (b1 > bb) : (b1 < bb)) continue;
                        unsigned int oo = which ? ~o : o;
                        unsigned long long kk =
                            ((unsigned long long)oo << 32) | (unsigned int)~j;
                        if (kk < thr && kk > lm) lm = kk;
                    }
                    thr = warpMaxBcast(lm);
                    if (lane == t) mykey = thr;
                }
            }
            float bs = 0.f;
            if (lane < k)
                bs = src[~(unsigned int)(mykey & 0xffffffffu)];
#pragma unroll
            for (int o = 16; o; o >>= 1)
                bs += __shfl_down_sync(0xffffffffu, bs, o);
            if (lane == 0) s_bs[which] = bs;
        }
        __syncthreads();

        // ---------- one fused reduction for the P1 sums ----------
        float v[8] = { syl, sul, kac, bub, bdb, 0.f, 0.f, 0.f };
        blockReduce8F(v, s_scf);
        syl = v[0]; sul = v[1]; kac = v[2]; bub = v[3]; bdb = v[4];

        float bu = bub - s_bs[0];
        float bd = bdb - s_bs[1];
        float kl = kac / syl + __logf(sul) - __logf(syl);
        loss = (bu + 0.5f * bd + 0.3f * kl) / (float)nv;
    }

    if (tid == 0) g_row[row] = loss;
    __threadfence();
    if (tid == 0) s_last = (atomicAdd(&g_ctr, 1u) == gridDim.x - 1u);
    __syncthreads();

    // last CTA reduces all rows (deterministic order) and writes scalar
    if (s_last) {
        __threadfence();
        float s = 0.f;
        for (int i = tid; i < (int)gridDim.x; i += BT) s += g_row[i];
        float v[8] = { s, 0.f, 0.f, 0.f, 0.f, 0.f, 0.f, 0.f };
        blockReduce8F(v, s_scf);
        if (tid == 0) { out[0] = v[0] / (float)gridDim.x; g_ctr = 0u; }
    }
}

extern "C" void kernel_launch(void* const* d_in, const int* in_sizes, int n_in,
                              void* d_out, int out_size) {
    const float* up = (const float*)d_in[0];
    const float* dn = (const float*)d_in[1];
    const float* yt = (const float*)d_in[2];
    const int*   mk = (const int*)d_in[3];
    int B = in_sizes[0] / NCOLS;
    if (B > MAXB) B = MAXB;
    row_kernel<<<B, BT>>>(up, dn, yt, mk, (float*)d_out);
}